// round 9
// baseline (speedup 1.0000x reference)
#include <cuda_runtime.h>
#include <cuda_bf16.h>
#include <math.h>
#include <stdint.h>

#define NN     20000
#define EG     60000            // real edges
#define HH     4
#define CC     128
#define DD     512
#define BB     4
#define SS     12
#define NB     (BB*NN)           // 80000 rows (b,n)
#define NEDGE  (EG+NN)           // 80000 edges per batch incl self loops
#define MEDGE  (BB*EG)           // 240000 rows (b,e)

// ---------------- scratch (static device arrays; no allocation) ----------------
__device__ float g_x0 [NB*CC];
__device__ float g_xh [NB*DD];
__device__ float g_h1 [NB*DD];
__device__ float g_h2 [NB*DD];
__device__ float g_es [NB*HH];
__device__ float g_ed [NB*HH];
__device__ float g_m  [NB*HH];
__device__ float g_den[NB*HH];
__device__ float g_ef [(long)MEDGE*DD];
__device__ float g_agg[NB*DD];
__device__ float g_hn [NB*64];
__device__ float g_he [MEDGE*64];
// bf16x3 operands for the big edge GEMM
__device__ __nv_bfloat16 g_h2hi[(long)NB*DD];
__device__ __nv_bfloat16 g_h2lo[(long)NB*DD];
__device__ __nv_bfloat16 g_whi [DD * 2 * DD];   // pW^T hi : [512,1024]
__device__ __nv_bfloat16 g_wlo [DD * 2 * DD];   // pW^T lo : [512,1024]

// ---------------- helpers ----------------
__device__ __forceinline__ float fixnum(float x) {
    if (isnan(x)) return 0.f;
    if (isinf(x)) return x > 0.f ? 3.402823466e38f : -3.402823466e38f;
    return x;
}

__device__ __forceinline__ void atomicMaxFloat(float* addr, float val) {
    int* ia = (int*)addr;
    int old = *ia;
    while (__int_as_float(old) < val) {
        int assumed = old;
        old = atomicCAS(ia, assumed, __float_as_int(val));
        if (old == assumed) break;
    }
}

__device__ __forceinline__ void edge_sd(const int* __restrict__ ei, int j, int& s, int& d) {
    if (j < EG) { s = ei[j]; d = ei[EG + j]; }
    else        { s = j - EG; d = j - EG; }
}

__device__ __forceinline__ uint32_t smem_u32(const void* p) {
    uint32_t a;
    asm("{ .reg .u64 t; cvta.to.shared.u64 t, %1; cvt.u32.u64 %0, t; }" : "=r"(a) : "l"(p));
    return a;
}

__device__ __forceinline__ void ldsm_x4(uint32_t* r, uint32_t addr) {
    asm volatile("ldmatrix.sync.aligned.m8n8.x4.shared.b16 {%0,%1,%2,%3}, [%4];"
                 : "=r"(r[0]), "=r"(r[1]), "=r"(r[2]), "=r"(r[3]) : "r"(addr));
}
__device__ __forceinline__ void ldsm_x2(uint32_t* r, uint32_t addr) {
    asm volatile("ldmatrix.sync.aligned.m8n8.x2.shared.b16 {%0,%1}, [%2];"
                 : "=r"(r[0]), "=r"(r[1]) : "r"(addr));
}
__device__ __forceinline__ void mma_bf16(float* c, const uint32_t* a, const uint32_t* b) {
    asm volatile(
        "mma.sync.aligned.m16n8k16.row.col.f32.bf16.bf16.f32 "
        "{%0,%1,%2,%3}, {%4,%5,%6,%7}, {%8,%9}, {%0,%1,%2,%3};"
        : "+f"(c[0]), "+f"(c[1]), "+f"(c[2]), "+f"(c[3])
        : "r"(a[0]), "r"(a[1]), "r"(a[2]), "r"(a[3]), "r"(b[0]), "r"(b[1]));
}

// ---------------- small kernels ----------------
__global__ void fill_kernel(float* p, float v, int n) {
    int t = blockIdx.x * blockDim.x + threadIdx.x;
    if (t < n) p[t] = v;
}

__global__ void build_x(const float* __restrict__ v, const float* __restrict__ p,
                        const float* __restrict__ q, const float* __restrict__ Win,
                        const float* __restrict__ bin) {
    int t = blockIdx.x * blockDim.x + threadIdx.x;
    if (t >= NB * CC) return;
    int c = t % CC;
    int r = t / CC;
    int b = r / NN, n = r % NN;
    int off = (b * SS + (SS - 1)) * NN + n;
    float vv = fixnum(v[off]);
    float pp = fixnum(p[off]);
    float qq = fixnum(q[off]);
    g_x0[t] = vv * Win[c] + pp * Win[CC + c] + qq * Win[2 * CC + c] + bin[c];
}

__global__ void es_ed_kernel(const float* __restrict__ xh,
                             const float* __restrict__ a_s,
                             const float* __restrict__ a_d) {
    int w = (blockIdx.x * blockDim.x + threadIdx.x) >> 5;
    int lane = threadIdx.x & 31;
    if (w >= NB * HH) return;
    int h = w % HH;
    long r = w / HH;
    float4 x4  = ((const float4*)(xh + r * DD + h * CC))[lane];
    float4 as4 = ((const float4*)(a_s + h * CC))[lane];
    float4 ad4 = ((const float4*)(a_d + h * CC))[lane];
    float s = x4.x*as4.x + x4.y*as4.y + x4.z*as4.z + x4.w*as4.w;
    float d = x4.x*ad4.x + x4.y*ad4.y + x4.z*ad4.z + x4.w*ad4.w;
    #pragma unroll
    for (int o = 16; o > 0; o >>= 1) {
        s += __shfl_xor_sync(0xffffffffu, s, o);
        d += __shfl_xor_sync(0xffffffffu, d, o);
    }
    if (lane == 0) { g_es[w] = s; g_ed[w] = d; }
}

__global__ void edge_max(const int* __restrict__ ei) {
    int t = blockIdx.x * blockDim.x + threadIdx.x;
    if (t >= BB * NEDGE * HH) return;
    int h = t % HH;
    int j = (t / HH) % NEDGE;
    int b = t / (HH * NEDGE);
    int s, d; edge_sd(ei, j, s, d);
    float e = g_es[(b * NN + s) * HH + h] + g_ed[(b * NN + d) * HH + h];
    e = e > 0.f ? e : 0.2f * e;
    atomicMaxFloat(&g_m[(b * NN + d) * HH + h], e);
}

__global__ void edge_den(const int* __restrict__ ei) {
    int t = blockIdx.x * blockDim.x + threadIdx.x;
    if (t >= BB * NEDGE * HH) return;
    int h = t % HH;
    int j = (t / HH) % NEDGE;
    int b = t / (HH * NEDGE);
    int s, d; edge_sd(ei, j, s, d);
    int di = (b * NN + d) * HH + h;
    float e = g_es[(b * NN + s) * HH + h] + g_ed[di];
    e = e > 0.f ? e : 0.2f * e;
    atomicAdd(&g_den[di], expf(e - g_m[di]));
}

__global__ void edge_agg(const int* __restrict__ ei, const float* __restrict__ xh) {
    int w = (blockIdx.x * blockDim.x + threadIdx.x) >> 5;
    int lane = threadIdx.x & 31;
    if (w >= BB * NEDGE * HH) return;
    int h = w % HH;
    int j = (w / HH) % NEDGE;
    int b = w / (HH * NEDGE);
    int s, d; edge_sd(ei, j, s, d);
    int di = (b * NN + d) * HH + h;
    float e = g_es[(b * NN + s) * HH + h] + g_ed[di];
    e = e > 0.f ? e : 0.2f * e;
    float alpha = expf(e - g_m[di]) / (g_den[di] + 1e-16f);
    const float* xr = xh + ((long)(b * NN + s)) * DD + h * CC;
    float* ar = g_agg + ((long)(b * NN + d)) * DD + h * CC;
    #pragma unroll
    for (int k = 0; k < 4; k++) {
        int c = lane + 32 * k;
        atomicAdd(&ar[c], alpha * xr[c]);
    }
}

__global__ void bias_relu(const float* __restrict__ bvec, float* __restrict__ out) {
    int t = blockIdx.x * blockDim.x + threadIdx.x;
    if (t >= NB * DD) return;
    float v = g_agg[t] + bvec[t % DD];
    out[t] = v > 0.f ? v : 0.f;
}

// fp32 -> (bf16 hi, bf16 lo) split
__global__ void conv_split(const float* __restrict__ x, __nv_bfloat16* __restrict__ hi,
                           __nv_bfloat16* __restrict__ lo, long n) {
    long t = (long)blockIdx.x * blockDim.x + threadIdx.x;
    if (t >= n) return;
    float v = x[t];
    __nv_bfloat16 h = __float2bfloat16(v);
    hi[t] = h;
    lo[t] = __float2bfloat16(v - __bfloat162float(h));
}

// pW [1024,512] fp32 -> transposed [512,1024] bf16 hi/lo
__global__ void conv_w_t(const float* __restrict__ w, __nv_bfloat16* __restrict__ hi,
                         __nv_bfloat16* __restrict__ lo) {
    int t = blockIdx.x * blockDim.x + threadIdx.x;
    if (t >= 1024 * 512) return;
    int k = t / 512, n = t % 512;
    float v = w[t];
    __nv_bfloat16 h = __float2bfloat16(v);
    int o = n * 1024 + k;
    hi[o] = h;
    lo[o] = __float2bfloat16(v - __bfloat162float(h));
}

// ---------------- mma.sync bf16x3 GEMM for the edge projection ----------------
// C[m, n] = sum_k concat(h2[src_m], h2[dst_m])[k] * pW[k, n] + pb[n]
// CTA tile 128(M) x 128(N), K chunks of 32. 8 warps in 4(m) x 2(n) grid,
// each warp owns 32x64 via m16n8k16 fragments.
#define KC    32
#define PITCH 80   // bytes per smem row: 64 data + 16 pad (conflict-free ldmatrix)

__global__ __launch_bounds__(256, 1)
void edge_mma(const int* __restrict__ ei,
              const __nv_bfloat16* __restrict__ h2hi,
              const __nv_bfloat16* __restrict__ h2lo,
              const __nv_bfloat16* __restrict__ whi,
              const __nv_bfloat16* __restrict__ wlo,
              const float* __restrict__ pb,
              float* __restrict__ C)
{
    __shared__ char sAh[128 * PITCH];
    __shared__ char sAl[128 * PITCH];
    __shared__ char sBh[128 * PITCH];
    __shared__ char sBl[128 * PITCH];
    __shared__ int rsrc[128];
    __shared__ int rdst[128];

    const int tid  = threadIdx.x;
    const int lane = tid & 31;
    const int wid  = tid >> 5;
    const int r0 = blockIdx.y * 128;
    const int n0 = blockIdx.x * 128;

    if (tid < 128) {
        int m = r0 + tid;
        int b = m / EG;
        int e = m - b * EG;
        rsrc[tid] = (b * NN + ei[e]) * DD;
        rdst[tid] = (b * NN + ei[EG + e]) * DD;
    }
    __syncthreads();

    const int wm = wid & 3;    // m block of 32
    const int wn = wid >> 2;   // n block of 64

    float acc[2][8][4];
    #pragma unroll
    for (int i = 0; i < 2; i++)
        #pragma unroll
        for (int j = 0; j < 8; j++)
            #pragma unroll
            for (int q = 0; q < 4; q++) acc[i][j][q] = 0.f;

    const int arow  = tid >> 1;
    const int apart = tid & 1;

    const uint32_t uAh = smem_u32(sAh);
    const uint32_t uAl = smem_u32(sAl);
    const uint32_t uBh = smem_u32(sBh);
    const uint32_t uBl = smem_u32(sBl);

    // per-warp ldmatrix addresses (constant across k loop except k column offset)
    const uint32_t a_roff = (uint32_t)((wm * 32 + (lane & 15)) * PITCH + (lane >> 4) * 16);

    for (int k0 = 0; k0 < 2 * DD; k0 += KC) {
        // ---- global loads (2 threads per row, 2 x int4 each, hi+lo) ----
        int abase = (k0 < DD) ? (rsrc[arow] + k0) : (rdst[arow] + (k0 - DD));
        const int4* gah = (const int4*)(h2hi + abase);
        const int4* gal = (const int4*)(h2lo + abase);
        int4 ah0 = __ldg(gah + apart), ah1 = __ldg(gah + apart + 2);
        int4 al0 = __ldg(gal + apart), al1 = __ldg(gal + apart + 2);

        long bbase = (long)(n0 + arow) * (2 * DD) + k0;
        const int4* gbh = (const int4*)(whi + bbase);
        const int4* gbl = (const int4*)(wlo + bbase);
        int4 bh0 = __ldg(gbh + apart), bh1 = __ldg(gbh + apart + 2);
        int4 bl0 = __ldg(gbl + apart), bl1 = __ldg(gbl + apart + 2);

        __syncthreads();   // previous iteration's ldmatrix reads done

        {
            char* pA = sAh + arow * PITCH + apart * 16;
            *(int4*)(pA) = ah0;  *(int4*)(pA + 32) = ah1;
            char* pL = sAl + arow * PITCH + apart * 16;
            *(int4*)(pL) = al0;  *(int4*)(pL + 32) = al1;
            char* pB = sBh + arow * PITCH + apart * 16;
            *(int4*)(pB) = bh0;  *(int4*)(pB + 32) = bh1;
            char* pC = sBl + arow * PITCH + apart * 16;
            *(int4*)(pC) = bl0;  *(int4*)(pC + 32) = bl1;
        }
        __syncthreads();

        // ---- tensor math ----
        #pragma unroll
        for (int kk = 0; kk < 2; kk++) {
            uint32_t afh[2][4], afl[2][4];
            #pragma unroll
            for (int mi = 0; mi < 2; mi++) {
                uint32_t off = a_roff + (uint32_t)(mi * 16 * PITCH + kk * 32);
                ldsm_x4(afh[mi], uAh + off);
                ldsm_x4(afl[mi], uAl + off);
            }
            #pragma unroll
            for (int nj = 0; nj < 8; nj++) {
                uint32_t boff = (uint32_t)((wn * 64 + nj * 8 + (lane & 7)) * PITCH
                                           + kk * 32 + ((lane & 8) ? 16 : 0));
                uint32_t bfh[2], bfl[2];
                ldsm_x2(bfh, uBh + boff);
                ldsm_x2(bfl, uBl + boff);
                #pragma unroll
                for (int mi = 0; mi < 2; mi++) {
                    mma_bf16(acc[mi][nj], afh[mi], bfh);
                    mma_bf16(acc[mi][nj], afh[mi], bfl);
                    mma_bf16(acc[mi][nj], afl[mi], bfh);
                }
            }
        }
    }

    // ---- epilogue: c0,c1 -> row m, cols n,n+1 ; c2,c3 -> row m+8 ----
    const int mrow = r0 + wm * 32 + (lane >> 2);
    const int ncol = n0 + wn * 64 + (lane & 3) * 2;
    #pragma unroll
    for (int mi = 0; mi < 2; mi++) {
        #pragma unroll
        for (int nj = 0; nj < 8; nj++) {
            int col = ncol + nj * 8;
            float b0 = pb[col], b1 = pb[col + 1];
            long base0 = (long)(mrow + mi * 16) * DD + col;
            long base1 = (long)(mrow + mi * 16 + 8) * DD + col;
            *(float2*)(C + base0) = make_float2(acc[mi][nj][0] + b0, acc[mi][nj][1] + b1);
            *(float2*)(C + base1) = make_float2(acc[mi][nj][2] + b0, acc[mi][nj][3] + b1);
        }
    }
}

// ---------------- SGEMM 128x128x8, 256 threads, 8x8 per thread (fp32 path) ----------------
__global__ __launch_bounds__(256)
void sgemm(int M, int N, int K,
           const float* __restrict__ A,
           const float* __restrict__ B,
           const float* __restrict__ bias,
           float* __restrict__ C,
           int do_relu)
{
    __shared__ float As[8][128];
    __shared__ float Bs[8][128];
    int tid  = threadIdx.x;
    int row0 = blockIdx.y * 128;
    int col0 = blockIdx.x * 128;
    int tx = tid & 15, ty = tid >> 4;

    float acc[8][8];
    #pragma unroll
    for (int i = 0; i < 8; i++)
        #pragma unroll
        for (int j = 0; j < 8; j++) acc[i][j] = 0.f;

    int a_r = tid >> 1;
    int a_c = (tid & 1) << 2;
    int b_r = tid >> 5;
    int b_c = (tid & 31) << 2;

    const float* arow0 = A + (long)(row0 + a_r) * K;

    for (int k0 = 0; k0 < K; k0 += 8) {
        float4 av = *(const float4*)(arow0 + k0 + a_c);
        As[a_c + 0][a_r] = av.x; As[a_c + 1][a_r] = av.y;
        As[a_c + 2][a_r] = av.z; As[a_c + 3][a_r] = av.w;

        float4 bv = make_float4(0.f, 0.f, 0.f, 0.f);
        int gc = col0 + b_c;
        if (gc < N) bv = *(const float4*)(B + (long)(k0 + b_r) * N + gc);
        Bs[b_r][b_c + 0] = bv.x; Bs[b_r][b_c + 1] = bv.y;
        Bs[b_r][b_c + 2] = bv.z; Bs[b_r][b_c + 3] = bv.w;
        __syncthreads();

        #pragma unroll
        for (int k = 0; k < 8; k++) {
            float ra[8], rb[8];
            #pragma unroll
            for (int i = 0; i < 8; i++) ra[i] = As[k][ty * 8 + i];
            #pragma unroll
            for (int j = 0; j < 8; j++) rb[j] = Bs[k][tx * 8 + j];
            #pragma unroll
            for (int i = 0; i < 8; i++)
                #pragma unroll
                for (int j = 0; j < 8; j++)
                    acc[i][j] = fmaf(ra[i], rb[j], acc[i][j]);
        }
        __syncthreads();
    }

    #pragma unroll
    for (int i = 0; i < 8; i++) {
        long r = row0 + ty * 8 + i;
        #pragma unroll
        for (int j = 0; j < 8; j++) {
            int c = col0 + tx * 8 + j;
            if (c < N) {
                float v = acc[i][j];
                if (bias) v += bias[c];
                if (do_relu) v = v > 0.f ? v : 0.f;
                C[r * N + c] = v;
            }
        }
    }
}

// ---------------- heads ----------------
__global__ void node_out(const float* __restrict__ sW2, const float* __restrict__ sb2,
                         float* __restrict__ out) {
    int r = blockIdx.x * blockDim.x + threadIdx.x;
    if (r >= NB) return;
    float s0 = sb2[0], s1 = sb2[1];
    const float* hr = g_hn + (long)r * 64;
    #pragma unroll
    for (int k = 0; k < 64; k++) {
        float hv = hr[k];
        s0 += hv * sW2[2 * k];
        s1 += hv * sW2[2 * k + 1];
    }
    out[r]      = 1.f / (1.f + expf(-s0)) * 0.3f + 0.85f;
    out[NB + r] = tanhf(s1) * 0.5f;
}

__global__ void edge_out(const float* __restrict__ hW2, const float* __restrict__ hb2,
                         float* __restrict__ out) {
    int r = blockIdx.x * blockDim.x + threadIdx.x;
    if (r >= MEDGE) return;
    float s0 = hb2[0], s1 = hb2[1];
    const float* hr = g_he + (long)r * 64;
    #pragma unroll
    for (int k = 0; k < 64; k++) {
        float hv = hr[k];
        s0 += hv * hW2[2 * k];
        s1 += hv * hW2[2 * k + 1];
    }
    out[2 * NB + r]         = 1.f / (1.f + expf(-s0)) * 2.99f + 0.01f;
    out[2 * NB + MEDGE + r] = 1.f / (1.f + expf(-s1)) * 2.99f + 0.01f;
}

// ---------------- host orchestration ----------------
static void gat_layer(const float* xin, int Fin,
                      const float* W, const float* a_s, const float* a_d, const float* bvec,
                      const int* ei,
                      float* xh, float* mptr, float* denptr, float* aggptr, float* hout)
{
    dim3 gg((DD + 127) / 128, NB / 128);
    sgemm<<<gg, 256>>>(NB, DD, Fin, xin, W, nullptr, xh, 0);

    es_ed_kernel<<<(NB * HH * 32 + 255) / 256, 256>>>(xh, a_s, a_d);

    fill_kernel<<<(NB * HH + 255) / 256, 256>>>(mptr, -1e30f, NB * HH);
    cudaMemsetAsync(denptr, 0, (size_t)NB * HH * sizeof(float), 0);
    cudaMemsetAsync(aggptr, 0, (size_t)NB * DD * sizeof(float), 0);

    int et = BB * NEDGE * HH;
    edge_max<<<(et + 255) / 256, 256>>>(ei);
    edge_den<<<(et + 255) / 256, 256>>>(ei);
    edge_agg<<<((long)et * 32 + 255) / 256, 256>>>(ei, xh);

    bias_relu<<<(NB * DD + 255) / 256, 256>>>(bvec, hout);
}

extern "C" void kernel_launch(void* const* d_in, const int* in_sizes, int n_in,
                              void* d_out, int out_size) {
    const float* v_mag = (const float*)d_in[0];
    const float* p_bus = (const float*)d_in[1];
    const float* q_bus = (const float*)d_in[2];
    const int*   ei    = (const int*)  d_in[3];
    const float* W_in  = (const float*)d_in[4];
    const float* b_in  = (const float*)d_in[5];
    const float* g1W   = (const float*)d_in[6];
    const float* g1as  = (const float*)d_in[7];
    const float* g1ad  = (const float*)d_in[8];
    const float* g1b   = (const float*)d_in[9];
    const float* g2W   = (const float*)d_in[10];
    const float* g2as  = (const float*)d_in[11];
    const float* g2ad  = (const float*)d_in[12];
    const float* g2b   = (const float*)d_in[13];
    const float* sW1   = (const float*)d_in[14];
    const float* sb1   = (const float*)d_in[15];
    const float* sW2   = (const float*)d_in[16];
    const float* sb2   = (const float*)d_in[17];
    const float* pW    = (const float*)d_in[18];
    const float* pb    = (const float*)d_in[19];
    const float* hW1   = (const float*)d_in[20];
    const float* hb1   = (const float*)d_in[21];
    const float* hW2   = (const float*)d_in[22];
    const float* hb2   = (const float*)d_in[23];
    float* out = (float*)d_out;

    float *x0, *xh, *h1, *h2, *mptr, *denptr, *aggptr, *ef, *hn, *he;
    __nv_bfloat16 *h2hi, *h2lo, *whi, *wlo;
    cudaGetSymbolAddress((void**)&x0,  g_x0);
    cudaGetSymbolAddress((void**)&xh,  g_xh);
    cudaGetSymbolAddress((void**)&h1,  g_h1);
    cudaGetSymbolAddress((void**)&h2,  g_h2);
    cudaGetSymbolAddress((void**)&mptr,   g_m);
    cudaGetSymbolAddress((void**)&denptr, g_den);
    cudaGetSymbolAddress((void**)&aggptr, g_agg);
    cudaGetSymbolAddress((void**)&ef,  g_ef);
    cudaGetSymbolAddress((void**)&hn,  g_hn);
    cudaGetSymbolAddress((void**)&he,  g_he);
    cudaGetSymbolAddress((void**)&h2hi, g_h2hi);
    cudaGetSymbolAddress((void**)&h2lo, g_h2lo);
    cudaGetSymbolAddress((void**)&whi,  g_whi);
    cudaGetSymbolAddress((void**)&wlo,  g_wlo);

    // input embedding
    build_x<<<(NB * CC + 255) / 256, 256>>>(v_mag, p_bus, q_bus, W_in, b_in);

    // weight split+transpose for the edge GEMM (independent; issue early)
    conv_w_t<<<(1024 * 512 + 255) / 256, 256>>>(pW, whi, wlo);

    // two GAT layers
    gat_layer(x0, CC, g1W, g1as, g1ad, g1b, ei, xh, mptr, denptr, aggptr, h1);
    gat_layer(h1, DD, g2W, g2as, g2ad, g2b, ei, xh, mptr, denptr, aggptr, h2);

    // node head
    {
        dim3 gg(1, NB / 128);
        sgemm<<<gg, 256>>>(NB, 64, DD, h2, sW1, sb1, hn, 1);
        node_out<<<(NB + 255) / 256, 256>>>(sW2, sb2, out);
    }

    // edge head: bf16x3 tensor-core GEMM for the 240000x512x1024 projection
    {
        conv_split<<<(int)(((long)NB * DD + 255) / 256), 256>>>(h2, h2hi, h2lo, (long)NB * DD);
        edge_mma<<<dim3(DD / 128, MEDGE / 128), 256>>>(ei, h2hi, h2lo, whi, wlo, pb, ef);

        dim3 g2d(1, MEDGE / 128);
        sgemm<<<g2d, 256>>>(MEDGE, 64, DD, ef, hW1, hb1, he, 1);
        edge_out<<<(MEDGE + 255) / 256, 256>>>(hW2, hb2, out);
    }
}

// round 10
// speedup vs baseline: 1.0008x; 1.0008x over previous
#include <cuda_runtime.h>
#include <cuda_bf16.h>
#include <math.h>
#include <stdint.h>

#define NN     20000
#define EG     60000            // real edges
#define HH     4
#define CC     128
#define DD     512
#define BB     4
#define SS     12
#define NB     (BB*NN)           // 80000 rows (b,n)
#define NEDGE  (EG+NN)           // 80000 edges per batch incl self loops
#define MEDGE  (BB*EG)           // 240000 rows (b,e)

// ---------------- scratch (static device arrays; no allocation) ----------------
__device__ float g_x0 [NB*CC];
__device__ float g_xh [NB*DD];
__device__ float g_h1 [NB*DD];
__device__ float g_h2 [NB*DD];
__device__ float g_es [NB*HH];
__device__ float g_ed [NB*HH];
__device__ float g_m  [NB*HH];
__device__ float g_den[NB*HH];
__device__ float g_ef [(long)MEDGE*DD];
__device__ float g_agg[NB*DD];
__device__ float g_hn [NB*64];
__device__ float g_he [MEDGE*64];
// bf16x3 operands for the big edge GEMM
__device__ __nv_bfloat16 g_h2hi[(long)NB*DD];
__device__ __nv_bfloat16 g_h2lo[(long)NB*DD];
__device__ __nv_bfloat16 g_whi [DD * 2 * DD];   // pW^T hi : [512,1024]
__device__ __nv_bfloat16 g_wlo [DD * 2 * DD];   // pW^T lo : [512,1024]

// ---------------- helpers ----------------
__device__ __forceinline__ float fixnum(float x) {
    if (isnan(x)) return 0.f;
    if (isinf(x)) return x > 0.f ? 3.402823466e38f : -3.402823466e38f;
    return x;
}

__device__ __forceinline__ void atomicMaxFloat(float* addr, float val) {
    int* ia = (int*)addr;
    int old = *ia;
    while (__int_as_float(old) < val) {
        int assumed = old;
        old = atomicCAS(ia, assumed, __float_as_int(val));
        if (old == assumed) break;
    }
}

__device__ __forceinline__ void edge_sd(const int* __restrict__ ei, int j, int& s, int& d) {
    if (j < EG) { s = ei[j]; d = ei[EG + j]; }
    else        { s = j - EG; d = j - EG; }
}

__device__ __forceinline__ uint32_t smem_u32(const void* p) {
    uint32_t a;
    asm("{ .reg .u64 t; cvta.to.shared.u64 t, %1; cvt.u32.u64 %0, t; }" : "=r"(a) : "l"(p));
    return a;
}

__device__ __forceinline__ void ldsm_x4(uint32_t* r, uint32_t addr) {
    asm volatile("ldmatrix.sync.aligned.m8n8.x4.shared.b16 {%0,%1,%2,%3}, [%4];"
                 : "=r"(r[0]), "=r"(r[1]), "=r"(r[2]), "=r"(r[3]) : "r"(addr));
}
__device__ __forceinline__ void ldsm_x2(uint32_t* r, uint32_t addr) {
    asm volatile("ldmatrix.sync.aligned.m8n8.x2.shared.b16 {%0,%1}, [%2];"
                 : "=r"(r[0]), "=r"(r[1]) : "r"(addr));
}
__device__ __forceinline__ void mma_bf16(float* c, const uint32_t* a, const uint32_t* b) {
    asm volatile(
        "mma.sync.aligned.m16n8k16.row.col.f32.bf16.bf16.f32 "
        "{%0,%1,%2,%3}, {%4,%5,%6,%7}, {%8,%9}, {%0,%1,%2,%3};"
        : "+f"(c[0]), "+f"(c[1]), "+f"(c[2]), "+f"(c[3])
        : "r"(a[0]), "r"(a[1]), "r"(a[2]), "r"(a[3]), "r"(b[0]), "r"(b[1]));
}

// ---------------- small kernels ----------------
__global__ void fill_kernel(float* p, float v, int n) {
    int t = blockIdx.x * blockDim.x + threadIdx.x;
    if (t < n) p[t] = v;
}

__global__ void build_x(const float* __restrict__ v, const float* __restrict__ p,
                        const float* __restrict__ q, const float* __restrict__ Win,
                        const float* __restrict__ bin) {
    int t = blockIdx.x * blockDim.x + threadIdx.x;
    if (t >= NB * CC) return;
    int c = t % CC;
    int r = t / CC;
    int b = r / NN, n = r % NN;
    int off = (b * SS + (SS - 1)) * NN + n;
    float vv = fixnum(v[off]);
    float pp = fixnum(p[off]);
    float qq = fixnum(q[off]);
    g_x0[t] = vv * Win[c] + pp * Win[CC + c] + qq * Win[2 * CC + c] + bin[c];
}

__global__ void es_ed_kernel(const float* __restrict__ xh,
                             const float* __restrict__ a_s,
                             const float* __restrict__ a_d) {
    int w = (blockIdx.x * blockDim.x + threadIdx.x) >> 5;
    int lane = threadIdx.x & 31;
    if (w >= NB * HH) return;
    int h = w % HH;
    long r = w / HH;
    float4 x4  = ((const float4*)(xh + r * DD + h * CC))[lane];
    float4 as4 = ((const float4*)(a_s + h * CC))[lane];
    float4 ad4 = ((const float4*)(a_d + h * CC))[lane];
    float s = x4.x*as4.x + x4.y*as4.y + x4.z*as4.z + x4.w*as4.w;
    float d = x4.x*ad4.x + x4.y*ad4.y + x4.z*ad4.z + x4.w*ad4.w;
    #pragma unroll
    for (int o = 16; o > 0; o >>= 1) {
        s += __shfl_xor_sync(0xffffffffu, s, o);
        d += __shfl_xor_sync(0xffffffffu, d, o);
    }
    if (lane == 0) { g_es[w] = s; g_ed[w] = d; }
}

__global__ void edge_max(const int* __restrict__ ei) {
    int t = blockIdx.x * blockDim.x + threadIdx.x;
    if (t >= BB * NEDGE * HH) return;
    int h = t % HH;
    int j = (t / HH) % NEDGE;
    int b = t / (HH * NEDGE);
    int s, d; edge_sd(ei, j, s, d);
    float e = g_es[(b * NN + s) * HH + h] + g_ed[(b * NN + d) * HH + h];
    e = e > 0.f ? e : 0.2f * e;
    atomicMaxFloat(&g_m[(b * NN + d) * HH + h], e);
}

__global__ void edge_den(const int* __restrict__ ei) {
    int t = blockIdx.x * blockDim.x + threadIdx.x;
    if (t >= BB * NEDGE * HH) return;
    int h = t % HH;
    int j = (t / HH) % NEDGE;
    int b = t / (HH * NEDGE);
    int s, d; edge_sd(ei, j, s, d);
    int di = (b * NN + d) * HH + h;
    float e = g_es[(b * NN + s) * HH + h] + g_ed[di];
    e = e > 0.f ? e : 0.2f * e;
    atomicAdd(&g_den[di], expf(e - g_m[di]));
}

__global__ void edge_agg(const int* __restrict__ ei, const float* __restrict__ xh) {
    int w = (blockIdx.x * blockDim.x + threadIdx.x) >> 5;
    int lane = threadIdx.x & 31;
    if (w >= BB * NEDGE * HH) return;
    int h = w % HH;
    int j = (w / HH) % NEDGE;
    int b = w / (HH * NEDGE);
    int s, d; edge_sd(ei, j, s, d);
    int di = (b * NN + d) * HH + h;
    float e = g_es[(b * NN + s) * HH + h] + g_ed[di];
    e = e > 0.f ? e : 0.2f * e;
    float alpha = expf(e - g_m[di]) / (g_den[di] + 1e-16f);
    const float* xr = xh + ((long)(b * NN + s)) * DD + h * CC;
    float* ar = g_agg + ((long)(b * NN + d)) * DD + h * CC;
    #pragma unroll
    for (int k = 0; k < 4; k++) {
        int c = lane + 32 * k;
        atomicAdd(&ar[c], alpha * xr[c]);
    }
}

__global__ void bias_relu(const float* __restrict__ bvec, float* __restrict__ out) {
    int t = blockIdx.x * blockDim.x + threadIdx.x;
    if (t >= NB * DD) return;
    float v = g_agg[t] + bvec[t % DD];
    out[t] = v > 0.f ? v : 0.f;
}

// fp32 -> (bf16 hi, bf16 lo) split
__global__ void conv_split(const float* __restrict__ x, __nv_bfloat16* __restrict__ hi,
                           __nv_bfloat16* __restrict__ lo, long n) {
    long t = (long)blockIdx.x * blockDim.x + threadIdx.x;
    if (t >= n) return;
    float v = x[t];
    __nv_bfloat16 h = __float2bfloat16(v);
    hi[t] = h;
    lo[t] = __float2bfloat16(v - __bfloat162float(h));
}

// pW [1024,512] fp32 -> transposed [512,1024] bf16 hi/lo
__global__ void conv_w_t(const float* __restrict__ w, __nv_bfloat16* __restrict__ hi,
                         __nv_bfloat16* __restrict__ lo) {
    int t = blockIdx.x * blockDim.x + threadIdx.x;
    if (t >= 1024 * 512) return;
    int k = t / 512, n = t % 512;
    float v = w[t];
    __nv_bfloat16 h = __float2bfloat16(v);
    int o = n * 1024 + k;
    hi[o] = h;
    lo[o] = __float2bfloat16(v - __bfloat162float(h));
}

// ---------------- mma.sync bf16x3 GEMM for the edge projection ----------------
// C[m, n] = sum_k concat(h2[src_m], h2[dst_m])[k] * pW[k, n] + pb[n]
// CTA tile 128(M) x 128(N), K chunks of 32. 8 warps in 4(m) x 2(n) grid,
// each warp owns 32x64 via m16n8k16 fragments.
#define KC    32
#define PITCH 80   // bytes per smem row: 64 data + 16 pad (conflict-free ldmatrix)

__global__ __launch_bounds__(256, 1)
void edge_mma(const int* __restrict__ ei,
              const __nv_bfloat16* __restrict__ h2hi,
              const __nv_bfloat16* __restrict__ h2lo,
              const __nv_bfloat16* __restrict__ whi,
              const __nv_bfloat16* __restrict__ wlo,
              const float* __restrict__ pb,
              float* __restrict__ C)
{
    __shared__ char sAh[128 * PITCH];
    __shared__ char sAl[128 * PITCH];
    __shared__ char sBh[128 * PITCH];
    __shared__ char sBl[128 * PITCH];
    __shared__ int rsrc[128];
    __shared__ int rdst[128];

    const int tid  = threadIdx.x;
    const int lane = tid & 31;
    const int wid  = tid >> 5;
    const int r0 = blockIdx.y * 128;
    const int n0 = blockIdx.x * 128;

    if (tid < 128) {
        int m = r0 + tid;
        int b = m / EG;
        int e = m - b * EG;
        rsrc[tid] = (b * NN + ei[e]) * DD;
        rdst[tid] = (b * NN + ei[EG + e]) * DD;
    }
    __syncthreads();

    const int wm = wid & 3;    // m block of 32
    const int wn = wid >> 2;   // n block of 64

    float acc[2][8][4];
    #pragma unroll
    for (int i = 0; i < 2; i++)
        #pragma unroll
        for (int j = 0; j < 8; j++)
            #pragma unroll
            for (int q = 0; q < 4; q++) acc[i][j][q] = 0.f;

    const int arow  = tid >> 1;
    const int apart = tid & 1;

    const uint32_t uAh = smem_u32(sAh);
    const uint32_t uAl = smem_u32(sAl);
    const uint32_t uBh = smem_u32(sBh);
    const uint32_t uBl = smem_u32(sBl);

    // per-warp ldmatrix addresses (constant across k loop except k column offset)
    const uint32_t a_roff = (uint32_t)((wm * 32 + (lane & 15)) * PITCH + (lane >> 4) * 16);

    for (int k0 = 0; k0 < 2 * DD; k0 += KC) {
        // ---- global loads (2 threads per row, 2 x int4 each, hi+lo) ----
        int abase = (k0 < DD) ? (rsrc[arow] + k0) : (rdst[arow] + (k0 - DD));
        const int4* gah = (const int4*)(h2hi + abase);
        const int4* gal = (const int4*)(h2lo + abase);
        int4 ah0 = __ldg(gah + apart), ah1 = __ldg(gah + apart + 2);
        int4 al0 = __ldg(gal + apart), al1 = __ldg(gal + apart + 2);

        long bbase = (long)(n0 + arow) * (2 * DD) + k0;
        const int4* gbh = (const int4*)(whi + bbase);
        const int4* gbl = (const int4*)(wlo + bbase);
        int4 bh0 = __ldg(gbh + apart), bh1 = __ldg(gbh + apart + 2);
        int4 bl0 = __ldg(gbl + apart), bl1 = __ldg(gbl + apart + 2);

        __syncthreads();   // previous iteration's ldmatrix reads done

        {
            char* pA = sAh + arow * PITCH + apart * 16;
            *(int4*)(pA) = ah0;  *(int4*)(pA + 32) = ah1;
            char* pL = sAl + arow * PITCH + apart * 16;
            *(int4*)(pL) = al0;  *(int4*)(pL + 32) = al1;
            char* pB = sBh + arow * PITCH + apart * 16;
            *(int4*)(pB) = bh0;  *(int4*)(pB + 32) = bh1;
            char* pC = sBl + arow * PITCH + apart * 16;
            *(int4*)(pC) = bl0;  *(int4*)(pC + 32) = bl1;
        }
        __syncthreads();

        // ---- tensor math ----
        #pragma unroll
        for (int kk = 0; kk < 2; kk++) {
            uint32_t afh[2][4], afl[2][4];
            #pragma unroll
            for (int mi = 0; mi < 2; mi++) {
                uint32_t off = a_roff + (uint32_t)(mi * 16 * PITCH + kk * 32);
                ldsm_x4(afh[mi], uAh + off);
                ldsm_x4(afl[mi], uAl + off);
            }
            #pragma unroll
            for (int nj = 0; nj < 8; nj++) {
                uint32_t boff = (uint32_t)((wn * 64 + nj * 8 + (lane & 7)) * PITCH
                                           + kk * 32 + ((lane & 8) ? 16 : 0));
                uint32_t bfh[2], bfl[2];
                ldsm_x2(bfh, uBh + boff);
                ldsm_x2(bfl, uBl + boff);
                #pragma unroll
                for (int mi = 0; mi < 2; mi++) {
                    mma_bf16(acc[mi][nj], afh[mi], bfh);
                    mma_bf16(acc[mi][nj], afh[mi], bfl);
                    mma_bf16(acc[mi][nj], afl[mi], bfh);
                }
            }
        }
    }

    // ---- epilogue: c0,c1 -> row m, cols n,n+1 ; c2,c3 -> row m+8 ----
    const int mrow = r0 + wm * 32 + (lane >> 2);
    const int ncol = n0 + wn * 64 + (lane & 3) * 2;
    #pragma unroll
    for (int mi = 0; mi < 2; mi++) {
        #pragma unroll
        for (int nj = 0; nj < 8; nj++) {
            int col = ncol + nj * 8;
            float b0 = pb[col], b1 = pb[col + 1];
            long base0 = (long)(mrow + mi * 16) * DD + col;
            long base1 = (long)(mrow + mi * 16 + 8) * DD + col;
            *(float2*)(C + base0) = make_float2(acc[mi][nj][0] + b0, acc[mi][nj][1] + b1);
            *(float2*)(C + base1) = make_float2(acc[mi][nj][2] + b0, acc[mi][nj][3] + b1);
        }
    }
}

// ---------------- SGEMM 128x128x8, 256 threads, 8x8 per thread (fp32 path) ----------------
__global__ __launch_bounds__(256)
void sgemm(int M, int N, int K,
           const float* __restrict__ A,
           const float* __restrict__ B,
           const float* __restrict__ bias,
           float* __restrict__ C,
           int do_relu)
{
    __shared__ float As[8][128];
    __shared__ float Bs[8][128];
    int tid  = threadIdx.x;
    int row0 = blockIdx.y * 128;
    int col0 = blockIdx.x * 128;
    int tx = tid & 15, ty = tid >> 4;

    float acc[8][8];
    #pragma unroll
    for (int i = 0; i < 8; i++)
        #pragma unroll
        for (int j = 0; j < 8; j++) acc[i][j] = 0.f;

    int a_r = tid >> 1;
    int a_c = (tid & 1) << 2;
    int b_r = tid >> 5;
    int b_c = (tid & 31) << 2;

    const float* arow0 = A + (long)(row0 + a_r) * K;

    for (int k0 = 0; k0 < K; k0 += 8) {
        float4 av = *(const float4*)(arow0 + k0 + a_c);
        As[a_c + 0][a_r] = av.x; As[a_c + 1][a_r] = av.y;
        As[a_c + 2][a_r] = av.z; As[a_c + 3][a_r] = av.w;

        float4 bv = make_float4(0.f, 0.f, 0.f, 0.f);
        int gc = col0 + b_c;
        if (gc < N) bv = *(const float4*)(B + (long)(k0 + b_r) * N + gc);
        Bs[b_r][b_c + 0] = bv.x; Bs[b_r][b_c + 1] = bv.y;
        Bs[b_r][b_c + 2] = bv.z; Bs[b_r][b_c + 3] = bv.w;
        __syncthreads();

        #pragma unroll
        for (int k = 0; k < 8; k++) {
            float ra[8], rb[8];
            #pragma unroll
            for (int i = 0; i < 8; i++) ra[i] = As[k][ty * 8 + i];
            #pragma unroll
            for (int j = 0; j < 8; j++) rb[j] = Bs[k][tx * 8 + j];
            #pragma unroll
            for (int i = 0; i < 8; i++)
                #pragma unroll
                for (int j = 0; j < 8; j++)
                    acc[i][j] = fmaf(ra[i], rb[j], acc[i][j]);
        }
        __syncthreads();
    }

    #pragma unroll
    for (int i = 0; i < 8; i++) {
        long r = row0 + ty * 8 + i;
        #pragma unroll
        for (int j = 0; j < 8; j++) {
            int c = col0 + tx * 8 + j;
            if (c < N) {
                float v = acc[i][j];
                if (bias) v += bias[c];
                if (do_relu) v = v > 0.f ? v : 0.f;
                C[r * N + c] = v;
            }
        }
    }
}

// ---------------- heads ----------------
__global__ void node_out(const float* __restrict__ sW2, const float* __restrict__ sb2,
                         float* __restrict__ out) {
    int r = blockIdx.x * blockDim.x + threadIdx.x;
    if (r >= NB) return;
    float s0 = sb2[0], s1 = sb2[1];
    const float* hr = g_hn + (long)r * 64;
    #pragma unroll
    for (int k = 0; k < 64; k++) {
        float hv = hr[k];
        s0 += hv * sW2[2 * k];
        s1 += hv * sW2[2 * k + 1];
    }
    out[r]      = 1.f / (1.f + expf(-s0)) * 0.3f + 0.85f;
    out[NB + r] = tanhf(s1) * 0.5f;
}

__global__ void edge_out(const float* __restrict__ hW2, const float* __restrict__ hb2,
                         float* __restrict__ out) {
    int r = blockIdx.x * blockDim.x + threadIdx.x;
    if (r >= MEDGE) return;
    float s0 = hb2[0], s1 = hb2[1];
    const float* hr = g_he + (long)r * 64;
    #pragma unroll
    for (int k = 0; k < 64; k++) {
        float hv = hr[k];
        s0 += hv * hW2[2 * k];
        s1 += hv * hW2[2 * k + 1];
    }
    out[2 * NB + r]         = 1.f / (1.f + expf(-s0)) * 2.99f + 0.01f;
    out[2 * NB + MEDGE + r] = 1.f / (1.f + expf(-s1)) * 2.99f + 0.01f;
}

// ---------------- host orchestration ----------------
static void gat_layer(const float* xin, int Fin,
                      const float* W, const float* a_s, const float* a_d, const float* bvec,
                      const int* ei,
                      float* xh, float* mptr, float* denptr, float* aggptr, float* hout)
{
    dim3 gg((DD + 127) / 128, NB / 128);
    sgemm<<<gg, 256>>>(NB, DD, Fin, xin, W, nullptr, xh, 0);

    es_ed_kernel<<<(NB * HH * 32 + 255) / 256, 256>>>(xh, a_s, a_d);

    fill_kernel<<<(NB * HH + 255) / 256, 256>>>(mptr, -1e30f, NB * HH);
    cudaMemsetAsync(denptr, 0, (size_t)NB * HH * sizeof(float), 0);
    cudaMemsetAsync(aggptr, 0, (size_t)NB * DD * sizeof(float), 0);

    int et = BB * NEDGE * HH;
    edge_max<<<(et + 255) / 256, 256>>>(ei);
    edge_den<<<(et + 255) / 256, 256>>>(ei);
    edge_agg<<<((long)et * 32 + 255) / 256, 256>>>(ei, xh);

    bias_relu<<<(NB * DD + 255) / 256, 256>>>(bvec, hout);
}

extern "C" void kernel_launch(void* const* d_in, const int* in_sizes, int n_in,
                              void* d_out, int out_size) {
    const float* v_mag = (const float*)d_in[0];
    const float* p_bus = (const float*)d_in[1];
    const float* q_bus = (const float*)d_in[2];
    const int*   ei    = (const int*)  d_in[3];
    const float* W_in  = (const float*)d_in[4];
    const float* b_in  = (const float*)d_in[5];
    const float* g1W   = (const float*)d_in[6];
    const float* g1as  = (const float*)d_in[7];
    const float* g1ad  = (const float*)d_in[8];
    const float* g1b   = (const float*)d_in[9];
    const float* g2W   = (const float*)d_in[10];
    const float* g2as  = (const float*)d_in[11];
    const float* g2ad  = (const float*)d_in[12];
    const float* g2b   = (const float*)d_in[13];
    const float* sW1   = (const float*)d_in[14];
    const float* sb1   = (const float*)d_in[15];
    const float* sW2   = (const float*)d_in[16];
    const float* sb2   = (const float*)d_in[17];
    const float* pW    = (const float*)d_in[18];
    const float* pb    = (const float*)d_in[19];
    const float* hW1   = (const float*)d_in[20];
    const float* hb1   = (const float*)d_in[21];
    const float* hW2   = (const float*)d_in[22];
    const float* hb2   = (const float*)d_in[23];
    float* out = (float*)d_out;

    float *x0, *xh, *h1, *h2, *mptr, *denptr, *aggptr, *ef, *hn, *he;
    __nv_bfloat16 *h2hi, *h2lo, *whi, *wlo;
    cudaGetSymbolAddress((void**)&x0,  g_x0);
    cudaGetSymbolAddress((void**)&xh,  g_xh);
    cudaGetSymbolAddress((void**)&h1,  g_h1);
    cudaGetSymbolAddress((void**)&h2,  g_h2);
    cudaGetSymbolAddress((void**)&mptr,   g_m);
    cudaGetSymbolAddress((void**)&denptr, g_den);
    cudaGetSymbolAddress((void**)&aggptr, g_agg);
    cudaGetSymbolAddress((void**)&ef,  g_ef);
    cudaGetSymbolAddress((void**)&hn,  g_hn);
    cudaGetSymbolAddress((void**)&he,  g_he);
    cudaGetSymbolAddress((void**)&h2hi, g_h2hi);
    cudaGetSymbolAddress((void**)&h2lo, g_h2lo);
    cudaGetSymbolAddress((void**)&whi,  g_whi);
    cudaGetSymbolAddress((void**)&wlo,  g_wlo);

    // input embedding
    build_x<<<(NB * CC + 255) / 256, 256>>>(v_mag, p_bus, q_bus, W_in, b_in);

    // weight split+transpose for the edge GEMM (independent; issue early)
    conv_w_t<<<(1024 * 512 + 255) / 256, 256>>>(pW, whi, wlo);

    // two GAT layers
    gat_layer(x0, CC, g1W, g1as, g1ad, g1b, ei, xh, mptr, denptr, aggptr, h1);
    gat_layer(h1, DD, g2W, g2as, g2ad, g2b, ei, xh, mptr, denptr, aggptr, h2);

    // node head
    {
        dim3 gg(1, NB / 128);
        sgemm<<<gg, 256>>>(NB, 64, DD, h2, sW1, sb1, hn, 1);
        node_out<<<(NB + 255) / 256, 256>>>(sW2, sb2, out);
    }

    // edge head: bf16x3 tensor-core GEMM for the 240000x512x1024 projection
    {
        conv_split<<<(int)(((long)NB * DD + 255) / 256), 256>>>(h2, h2hi, h2lo, (long)NB * DD);
        edge_mma<<<dim3(DD / 128, MEDGE / 128), 256>>>(ei, h2hi, h2lo, whi, wlo, pb, ef);

        dim3 g2d(1, MEDGE / 128);
        sgemm<<<g2d, 256>>>(MEDGE, 64, DD, ef, hW1, hb1, he, 1);
        edge_out<<<(MEDGE + 255) / 256, 256>>>(hW2, hb2, out);
    }
}